// round 9
// baseline (speedup 1.0000x reference)
#include <cuda_runtime.h>
#include <cuda_bf16.h>
#include <cstdint>

#define PLANES 80
#define FLAT   5120      // 80 * 64
#define NMOVES 1858
#define BATCH  16384
#define ROW_BYTES (FLAT * 4)   // 20480

#define TOTAL4      (FLAT * NMOVES / 4)   // 2,378,240 uint4
#define BUILD_GRID  148                   // 1 CTA/SM: leave room for gather CTAs
#define BUILD_STRIDE (BUILD_GRID * 256)   // 37,888 uint4 per sweep

// move -> flat-index map, rebuilt every launch (deterministic per call).
__device__ __align__(16) int g_idx[NMOVES];

// ---------------------------------------------------------------------------
// PTX helpers
// ---------------------------------------------------------------------------
__device__ __forceinline__ uint32_t smem_u32(const void* p) {
    uint32_t a;
    asm("{ .reg .u64 t; cvta.to.shared.u64 t, %1; cvt.u32.u64 %0, t; }"
        : "=r"(a) : "l"(p));
    return a;
}
__device__ __forceinline__ void mbar_init(uint32_t addr, uint32_t count) {
    asm volatile("mbarrier.init.shared.b64 [%0], %1;" :: "r"(addr), "r"(count) : "memory");
}
__device__ __forceinline__ void mbar_expect_tx(uint32_t addr, uint32_t bytes) {
    asm volatile("mbarrier.arrive.expect_tx.shared.b64 _, [%0], %1;"
                 :: "r"(addr), "r"(bytes) : "memory");
}
__device__ __forceinline__ void bulk_g2s(uint32_t dst_smem, const void* gsrc,
                                         uint32_t bytes, uint32_t mbar) {
    asm volatile(
        "cp.async.bulk.shared::cta.global.mbarrier::complete_tx::bytes "
        "[%0], [%1], %2, [%3];"
        :: "r"(dst_smem), "l"(gsrc), "r"(bytes), "r"(mbar) : "memory");
}
__device__ __forceinline__ void mbar_wait(uint32_t addr, uint32_t phase) {
    asm volatile(
        "{\n\t"
        ".reg .pred P;\n\t"
        "W%=:\n\t"
        "mbarrier.try_wait.parity.acquire.cta.shared::cta.b64 P, [%0], %1, 0x989680;\n\t"
        "@!P bra W%=;\n\t"
        "}"
        :: "r"(addr), "r"(phase) : "memory");
}
// PDL controls
__device__ __forceinline__ void pdl_launch_dependents() {
    asm volatile("griddepcontrol.launch_dependents;" ::: "memory");
}
__device__ __forceinline__ void pdl_wait() {
    asm volatile("griddepcontrol.wait;" ::: "memory");
}

// ---------------------------------------------------------------------------
// Kernel A: 0/1 selection-matrix scan, SMALL GRID (1 CTA/SM) so that the
// PDL-launched gather CTAs co-reside and overlap their TMA staging with this
// scan. Grid-stride, lane-contiguous, 8 independent uint4 loads in flight.
// ---------------------------------------------------------------------------
__global__ __launch_bounds__(256)
void build_idx_kernel(const uint4* __restrict__ fc1v) {
    pdl_launch_dependents();   // let gather CTAs fill the rest of each SM now

    const int start = blockIdx.x * 256 + threadIdx.x;

    for (int t0 = start; t0 < TOTAL4; t0 += 8 * BUILD_STRIDE) {
        #pragma unroll
        for (int j = 0; j < 8; j++) {
            const int t = t0 + j * BUILD_STRIDE;
            if (t < TOTAL4) {
                uint4 v = fc1v[t];
                if (v.x | v.y | v.z | v.w) {   // <=1858 hits in 9.5M elems
                    long long e = (long long)t * 4;
                    if (v.x) { long long ek = e;     g_idx[(int)(ek % NMOVES)] = (int)(ek / NMOVES); }
                    if (v.y) { long long ek = e + 1; g_idx[(int)(ek % NMOVES)] = (int)(ek / NMOVES); }
                    if (v.z) { long long ek = e + 2; g_idx[(int)(ek % NMOVES)] = (int)(ek / NMOVES); }
                    if (v.w) { long long ek = e + 3; g_idx[(int)(ek % NMOVES)] = (int)(ek / NMOVES); }
                }
            }
        }
    }
}

// ---------------------------------------------------------------------------
// Kernel B: out[b, m] = x[b, g_idx[m]].  (unchanged proven engine)
// One CTA per batch row. Issue the x-row TMA copy BEFORE griddepcontrol.wait,
// wait for build completion, read indices, gather from smem, float2 .cs stores.
// ---------------------------------------------------------------------------
__global__ __launch_bounds__(256)
void policy_gather_kernel(const float* __restrict__ x,
                          float* __restrict__ out) {
    __shared__ __align__(128) float row[FLAT];           // 20 KB
    __shared__ __align__(8) unsigned long long mbar;

    const int tid = threadIdx.x;
    const int b = blockIdx.x;
    const uint32_t mbar_a = smem_u32(&mbar);
    const uint32_t row_a  = smem_u32(row);

    if (tid == 0) mbar_init(mbar_a, 1);
    __syncthreads();
    if (tid == 0) {
        mbar_expect_tx(mbar_a, ROW_BYTES);
        bulk_g2s(row_a, x + (size_t)b * FLAT, ROW_BYTES, mbar_a);
    }

    // Block until the build grid has fully completed (g_idx visible).
    pdl_wait();

    // Preload gather indices (bulk copy possibly still in flight).
    const int2* idxp = reinterpret_cast<const int2*>(g_idx);
    const int2 i0 = idxp[tid];
    const int2 i1 = idxp[tid + 256];
    const int2 i2 = idxp[tid + 512];
    const bool has3 = tid < (NMOVES / 2 - 768);          // 161 threads
    int2 i3 = make_int2(0, 0);
    if (has3) i3 = idxp[tid + 768];

    mbar_wait(mbar_a, 0);

    float2* o = reinterpret_cast<float2*>(out + (size_t)b * NMOVES);
    float2 v;
    v.x = row[i0.x]; v.y = row[i0.y]; __stcs(o + tid,       v);
    v.x = row[i1.x]; v.y = row[i1.y]; __stcs(o + tid + 256, v);
    v.x = row[i2.x]; v.y = row[i2.y]; __stcs(o + tid + 512, v);
    if (has3) {
        v.x = row[i3.x]; v.y = row[i3.y]; __stcs(o + tid + 768, v);
    }
}

extern "C" void kernel_launch(void* const* d_in, const int* in_sizes, int n_in,
                              void* d_out, int out_size) {
    const float* x   = (const float*)d_in[0];   // [16384, 80, 8, 8] fp32
    const float* fc1 = (const float*)d_in[1];   // [5120, 1858] fp32
    float* out = (float*)d_out;                 // [16384, 1858] fp32

    // A: selection-index scan on a 1-CTA/SM grid (leaves SM slots free).
    build_idx_kernel<<<BUILD_GRID, 256>>>(reinterpret_cast<const uint4*>(fc1));

    // B: gather, PDL so its CTAs co-reside with the scan and pre-stage x rows.
    cudaLaunchConfig_t cfg = {};
    cfg.gridDim  = dim3(BATCH);
    cfg.blockDim = dim3(256);
    cfg.dynamicSmemBytes = 0;
    cfg.stream = 0;
    cudaLaunchAttribute attr[1];
    attr[0].id = cudaLaunchAttributeProgrammaticStreamSerialization;
    attr[0].val.programmaticStreamSerializationAllowed = 1;
    cfg.attrs = attr;
    cfg.numAttrs = 1;
    cudaLaunchKernelEx(&cfg, policy_gather_kernel, x, out);
}

// round 11
// speedup vs baseline: 1.3522x; 1.3522x over previous
#include <cuda_runtime.h>
#include <cuda_bf16.h>
#include <cstdint>

#define PLANES 80
#define FLAT   5120      // 80 * 64
#define NMOVES 1858
#define BATCH  16384
#define ROW_BYTES (FLAT * 4)   // 20480

// move -> flat-index map, rebuilt every launch (deterministic per call).
__device__ __align__(16) int g_idx[NMOVES];

// ---------------------------------------------------------------------------
// PTX helpers
// ---------------------------------------------------------------------------
__device__ __forceinline__ uint32_t smem_u32(const void* p) {
    uint32_t a;
    asm("{ .reg .u64 t; cvta.to.shared.u64 t, %1; cvt.u32.u64 %0, t; }"
        : "=r"(a) : "l"(p));
    return a;
}
__device__ __forceinline__ void mbar_init(uint32_t addr, uint32_t count) {
    asm volatile("mbarrier.init.shared.b64 [%0], %1;" :: "r"(addr), "r"(count) : "memory");
}
__device__ __forceinline__ void mbar_expect_tx(uint32_t addr, uint32_t bytes) {
    asm volatile("mbarrier.arrive.expect_tx.shared.b64 _, [%0], %1;"
                 :: "r"(addr), "r"(bytes) : "memory");
}
__device__ __forceinline__ void bulk_g2s(uint32_t dst_smem, const void* gsrc,
                                         uint32_t bytes, uint32_t mbar) {
    asm volatile(
        "cp.async.bulk.shared::cta.global.mbarrier::complete_tx::bytes "
        "[%0], [%1], %2, [%3];"
        :: "r"(dst_smem), "l"(gsrc), "r"(bytes), "r"(mbar) : "memory");
}
__device__ __forceinline__ void mbar_wait(uint32_t addr, uint32_t phase) {
    asm volatile(
        "{\n\t"
        ".reg .pred P;\n\t"
        "W%=:\n\t"
        "mbarrier.try_wait.parity.acquire.cta.shared::cta.b64 P, [%0], %1, 0x989680;\n\t"
        "@!P bra W%=;\n\t"
        "}"
        :: "r"(addr), "r"(phase) : "memory");
}
// PDL controls
__device__ __forceinline__ void pdl_launch_dependents() {
    asm volatile("griddepcontrol.launch_dependents;" ::: "memory");
}
__device__ __forceinline__ void pdl_wait() {
    asm volatile("griddepcontrol.wait;" ::: "memory");
}
// 32B load with L2 evict_last (legal width on sm_103: .v4.b64)
struct U64x4 { unsigned long long a, b, c, d; };
__device__ __forceinline__ U64x4 ldg32_evict_last(const void* p) {
    U64x4 v;
    asm volatile("ld.global.nc.L2::evict_last.v4.b64 {%0,%1,%2,%3}, [%4];"
                 : "=l"(v.a), "=l"(v.b), "=l"(v.c), "=l"(v.d) : "l"(p));
    return v;
}

// ---------------------------------------------------------------------------
// Kernel A: recover src index per move column from the 0/1 selection matrix.
// Perfect tiling over 32B chunks: 929 blocks x 256 threads x 5 chunks =
// 1,189,120 chunks = 38,051,840 B exactly. Lane-contiguous (1024B per warp
// per load), 5 independent 32B loads in flight per thread. Loads carry
// L2::evict_last so fc1 stays L2-resident across graph replays.
// ---------------------------------------------------------------------------
__global__ __launch_bounds__(256)
void build_idx_kernel(const unsigned char* __restrict__ fc1b) {
    pdl_launch_dependents();

    // chunk index: each chunk = 32 bytes = 8 floats
    const int base = blockIdx.x * 1280 + threadIdx.x;   // 1280 = 256*5 chunks

    U64x4 v0 = ldg32_evict_last(fc1b + (size_t)(base         ) * 32);
    U64x4 v1 = ldg32_evict_last(fc1b + (size_t)(base +  256) * 32);
    U64x4 v2 = ldg32_evict_last(fc1b + (size_t)(base +  512) * 32);
    U64x4 v3 = ldg32_evict_last(fc1b + (size_t)(base +  768) * 32);
    U64x4 v4 = ldg32_evict_last(fc1b + (size_t)(base + 1024) * 32);

    #pragma unroll
    for (int j = 0; j < 5; j++) {
        U64x4 v = (j == 0) ? v0 : (j == 1) ? v1 : (j == 2) ? v2 : (j == 3) ? v3 : v4;
        if (v.a | v.b | v.c | v.d) {   // rare: <=1858 hits in 9.5M elems
            const long long e = ((long long)base + j * 256) * 8;  // float index
            unsigned long long w[4] = { v.a, v.b, v.c, v.d };
            #pragma unroll
            for (int q = 0; q < 4; q++) {
                if ((unsigned)(w[q] & 0xffffffffu)) {
                    long long ek = e + 2 * q;
                    g_idx[(int)(ek % NMOVES)] = (int)(ek / NMOVES);
                }
                if ((unsigned)(w[q] >> 32)) {
                    long long ek = e + 2 * q + 1;
                    g_idx[(int)(ek % NMOVES)] = (int)(ek / NMOVES);
                }
            }
        }
    }
}

// ---------------------------------------------------------------------------
// Kernel B: out[b, m] = x[b, g_idx[m]].  (proven 61.5us @ 87% DRAM engine)
// One CTA per batch row. Issue the x-row TMA copy BEFORE griddepcontrol.wait,
// wait for build completion, read indices, gather from smem, float2 .cs stores.
// ---------------------------------------------------------------------------
__global__ __launch_bounds__(256)
void policy_gather_kernel(const float* __restrict__ x,
                          float* __restrict__ out) {
    __shared__ __align__(128) float row[FLAT];           // 20 KB
    __shared__ __align__(8) unsigned long long mbar;

    const int tid = threadIdx.x;
    const int b = blockIdx.x;
    const uint32_t mbar_a = smem_u32(&mbar);
    const uint32_t row_a  = smem_u32(row);

    if (tid == 0) mbar_init(mbar_a, 1);
    __syncthreads();
    if (tid == 0) {
        mbar_expect_tx(mbar_a, ROW_BYTES);
        bulk_g2s(row_a, x + (size_t)b * FLAT, ROW_BYTES, mbar_a);
    }

    // Block until the build grid has fully completed (g_idx visible).
    pdl_wait();

    // Preload gather indices (bulk copy possibly still in flight).
    const int2* idxp = reinterpret_cast<const int2*>(g_idx);
    const int2 i0 = idxp[tid];
    const int2 i1 = idxp[tid + 256];
    const int2 i2 = idxp[tid + 512];
    const bool has3 = tid < (NMOVES / 2 - 768);          // 161 threads
    int2 i3 = make_int2(0, 0);
    if (has3) i3 = idxp[tid + 768];

    mbar_wait(mbar_a, 0);

    float2* o = reinterpret_cast<float2*>(out + (size_t)b * NMOVES);
    float2 v;
    v.x = row[i0.x]; v.y = row[i0.y]; __stcs(o + tid,       v);
    v.x = row[i1.x]; v.y = row[i1.y]; __stcs(o + tid + 256, v);
    v.x = row[i2.x]; v.y = row[i2.y]; __stcs(o + tid + 512, v);
    if (has3) {
        v.x = row[i3.x]; v.y = row[i3.y]; __stcs(o + tid + 768, v);
    }
}

extern "C" void kernel_launch(void* const* d_in, const int* in_sizes, int n_in,
                              void* d_out, int out_size) {
    const float* x   = (const float*)d_in[0];   // [16384, 80, 8, 8] fp32
    const float* fc1 = (const float*)d_in[1];   // [5120, 1858] fp32
    float* out = (float*)d_out;                 // [16384, 1858] fp32

    // A: rebuild the selection index (38 MB scan, perfectly tiled, L2-pinned).
    build_idx_kernel<<<929, 256>>>(reinterpret_cast<const unsigned char*>(fc1));

    // B: gather with programmatic dependent launch (prologue overlaps build).
    cudaLaunchConfig_t cfg = {};
    cfg.gridDim  = dim3(BATCH);
    cfg.blockDim = dim3(256);
    cfg.dynamicSmemBytes = 0;
    cfg.stream = 0;
    cudaLaunchAttribute attr[1];
    attr[0].id = cudaLaunchAttributeProgrammaticStreamSerialization;
    attr[0].val.programmaticStreamSerializationAllowed = 1;
    cfg.attrs = attr;
    cfg.numAttrs = 1;
    cudaLaunchKernelEx(&cfg, policy_gather_kernel, x, out);
}

// round 12
// speedup vs baseline: 1.3922x; 1.0296x over previous
#include <cuda_runtime.h>
#include <cuda_bf16.h>
#include <cstdint>

#define PLANES 80
#define FLAT   5120      // 80 * 64
#define NMOVES 1858
#define BATCH  16384
#define ROW_BYTES (FLAT * 4)   // 20480

// move -> flat-index map, rebuilt every launch (deterministic per call).
__device__ __align__(16) int g_idx[NMOVES];

// ---------------------------------------------------------------------------
// PTX helpers
// ---------------------------------------------------------------------------
__device__ __forceinline__ uint32_t smem_u32(const void* p) {
    uint32_t a;
    asm("{ .reg .u64 t; cvta.to.shared.u64 t, %1; cvt.u32.u64 %0, t; }"
        : "=r"(a) : "l"(p));
    return a;
}
__device__ __forceinline__ void mbar_init(uint32_t addr, uint32_t count) {
    asm volatile("mbarrier.init.shared.b64 [%0], %1;" :: "r"(addr), "r"(count) : "memory");
}
__device__ __forceinline__ void mbar_expect_tx(uint32_t addr, uint32_t bytes) {
    asm volatile("mbarrier.arrive.expect_tx.shared.b64 _, [%0], %1;"
                 :: "r"(addr), "r"(bytes) : "memory");
}
// bulk copy with evict-first L2 policy: x is single-use streaming data, so it
// must NOT displace the L2-resident fc1 between graph replays.
__device__ __forceinline__ void bulk_g2s_ef(uint32_t dst_smem, const void* gsrc,
                                            uint32_t bytes, uint32_t mbar) {
    unsigned long long pol;
    asm volatile("createpolicy.fractional.L2::evict_first.b64 %0, 1.0;" : "=l"(pol));
    asm volatile(
        "cp.async.bulk.shared::cta.global.mbarrier::complete_tx::bytes.L2::cache_hint "
        "[%0], [%1], %2, [%3], %4;"
        :: "r"(dst_smem), "l"(gsrc), "r"(bytes), "r"(mbar), "l"(pol) : "memory");
}
__device__ __forceinline__ void mbar_wait(uint32_t addr, uint32_t phase) {
    asm volatile(
        "{\n\t"
        ".reg .pred P;\n\t"
        "W%=:\n\t"
        "mbarrier.try_wait.parity.acquire.cta.shared::cta.b64 P, [%0], %1, 0x989680;\n\t"
        "@!P bra W%=;\n\t"
        "}"
        :: "r"(addr), "r"(phase) : "memory");
}
// PDL controls
__device__ __forceinline__ void pdl_launch_dependents() {
    asm volatile("griddepcontrol.launch_dependents;" ::: "memory");
}
__device__ __forceinline__ void pdl_wait() {
    asm volatile("griddepcontrol.wait;" ::: "memory");
}
// 32B load with L2 evict_last (legal width on sm_103: .v4.b64)
struct U64x4 { unsigned long long a, b, c, d; };
__device__ __forceinline__ U64x4 ldg32_evict_last(const void* p) {
    U64x4 v;
    asm volatile("ld.global.nc.L2::evict_last.v4.b64 {%0,%1,%2,%3}, [%4];"
                 : "=l"(v.a), "=l"(v.b), "=l"(v.c), "=l"(v.d) : "l"(p));
    return v;
}

// ---------------------------------------------------------------------------
// Kernel A: recover src index per move column from the 0/1 selection matrix.
// Perfect tiling over 32B chunks: 929 blocks x 256 threads x 5 chunks.
// evict_last keeps fc1 L2-resident across graph replays; the gather's traffic
// is all evict-first, so residency should now actually hold.
// ---------------------------------------------------------------------------
__global__ __launch_bounds__(256)
void build_idx_kernel(const unsigned char* __restrict__ fc1b) {
    pdl_launch_dependents();

    const int base = blockIdx.x * 1280 + threadIdx.x;   // 1280 = 256*5 chunks

    U64x4 v0 = ldg32_evict_last(fc1b + (size_t)(base         ) * 32);
    U64x4 v1 = ldg32_evict_last(fc1b + (size_t)(base +  256) * 32);
    U64x4 v2 = ldg32_evict_last(fc1b + (size_t)(base +  512) * 32);
    U64x4 v3 = ldg32_evict_last(fc1b + (size_t)(base +  768) * 32);
    U64x4 v4 = ldg32_evict_last(fc1b + (size_t)(base + 1024) * 32);

    #pragma unroll
    for (int j = 0; j < 5; j++) {
        U64x4 v = (j == 0) ? v0 : (j == 1) ? v1 : (j == 2) ? v2 : (j == 3) ? v3 : v4;
        if (v.a | v.b | v.c | v.d) {   // rare: <=1858 hits in 9.5M elems
            const long long e = ((long long)base + j * 256) * 8;  // float index
            unsigned long long w[4] = { v.a, v.b, v.c, v.d };
            #pragma unroll
            for (int q = 0; q < 4; q++) {
                if ((unsigned)(w[q] & 0xffffffffu)) {
                    long long ek = e + 2 * q;
                    g_idx[(int)(ek % NMOVES)] = (int)(ek / NMOVES);
                }
                if ((unsigned)(w[q] >> 32)) {
                    long long ek = e + 2 * q + 1;
                    g_idx[(int)(ek % NMOVES)] = (int)(ek / NMOVES);
                }
            }
        }
    }
}

// ---------------------------------------------------------------------------
// Kernel B: out[b, m] = x[b, g_idx[m]].  (proven 61.5us @ 87% DRAM engine)
// One CTA per batch row. Issue the x-row TMA copy (evict-first) BEFORE
// griddepcontrol.wait, wait for build, read indices, gather, .cs stores.
// ---------------------------------------------------------------------------
__global__ __launch_bounds__(256)
void policy_gather_kernel(const float* __restrict__ x,
                          float* __restrict__ out) {
    __shared__ __align__(128) float row[FLAT];           // 20 KB
    __shared__ __align__(8) unsigned long long mbar;

    const int tid = threadIdx.x;
    const int b = blockIdx.x;
    const uint32_t mbar_a = smem_u32(&mbar);
    const uint32_t row_a  = smem_u32(row);

    if (tid == 0) mbar_init(mbar_a, 1);
    __syncthreads();
    if (tid == 0) {
        mbar_expect_tx(mbar_a, ROW_BYTES);
        bulk_g2s_ef(row_a, x + (size_t)b * FLAT, ROW_BYTES, mbar_a);
    }

    // Block until the build grid has fully completed (g_idx visible).
    pdl_wait();

    // Preload gather indices (bulk copy possibly still in flight).
    const int2* idxp = reinterpret_cast<const int2*>(g_idx);
    const int2 i0 = idxp[tid];
    const int2 i1 = idxp[tid + 256];
    const int2 i2 = idxp[tid + 512];
    const bool has3 = tid < (NMOVES / 2 - 768);          // 161 threads
    int2 i3 = make_int2(0, 0);
    if (has3) i3 = idxp[tid + 768];

    mbar_wait(mbar_a, 0);

    float2* o = reinterpret_cast<float2*>(out + (size_t)b * NMOVES);
    float2 v;
    v.x = row[i0.x]; v.y = row[i0.y]; __stcs(o + tid,       v);
    v.x = row[i1.x]; v.y = row[i1.y]; __stcs(o + tid + 256, v);
    v.x = row[i2.x]; v.y = row[i2.y]; __stcs(o + tid + 512, v);
    if (has3) {
        v.x = row[i3.x]; v.y = row[i3.y]; __stcs(o + tid + 768, v);
    }
}

extern "C" void kernel_launch(void* const* d_in, const int* in_sizes, int n_in,
                              void* d_out, int out_size) {
    const float* x   = (const float*)d_in[0];   // [16384, 80, 8, 8] fp32
    const float* fc1 = (const float*)d_in[1];   // [5120, 1858] fp32
    float* out = (float*)d_out;                 // [16384, 1858] fp32

    // A: rebuild the selection index (38 MB scan, L2-pinned via evict_last).
    build_idx_kernel<<<929, 256>>>(reinterpret_cast<const unsigned char*>(fc1));

    // B: gather with programmatic dependent launch (prologue overlaps build).
    cudaLaunchConfig_t cfg = {};
    cfg.gridDim  = dim3(BATCH);
    cfg.blockDim = dim3(256);
    cfg.dynamicSmemBytes = 0;
    cfg.stream = 0;
    cudaLaunchAttribute attr[1];
    attr[0].id = cudaLaunchAttributeProgrammaticStreamSerialization;
    attr[0].val.programmaticStreamSerializationAllowed = 1;
    cfg.attrs = attr;
    cfg.numAttrs = 1;
    cudaLaunchKernelEx(&cfg, policy_gather_kernel, x, out);
}